// round 15
// baseline (speedup 1.0000x reference)
#include <cuda_runtime.h>

// ============================================================================
// STGCNEncoder — fused persistent kernel, v8 (pass-B byte halving).
// Only row 0 of the GCN output feeds the GRU.
//  Pass A: stream int64 dst as uint4 pairs; min-trick detects dst==0 edges AND
//          compacts lo-words into g_dstlo (12.8MB) with coalesced STG.128.
//  Pass B: scan g_dstlo (HALF the bytes of dst) with u8 presence table in smem
//          -> exact degrees of the ~34-node set (rare global atomics).
//  Model: every pass variant (R9-R13) ran at ~2.5TB/s bytes-read invariant;
//  halving pass-B bytes is the remaining lever.
//  G=296 (2 CTAs/SM), B=1024. 3 grid barriers. Encoder + gh overlap; blk0 tail.
// ============================================================================

#define G    296
#define B    1024
#define STR  (G * B)
#define CAP  2048
#define EMAX 4194304

__device__ unsigned long long g_bar;
__device__ int      g_cnt;
__device__ int      g_srcs[CAP];
__device__ int      g_nodecnt[CAP + 2];
__device__ unsigned g_dstlo[EMAX];          // compacted lo-words of dst (int64 path)
__device__ unsigned short g_pres[131072];   // fallback presence (cnt>253, rare)
__device__ float    g_ybuf[CAP + 1][128];
__device__ float    g_gh[768];

extern __shared__ char sMem[];              // u8 presence table (NPAD); tail reuse

__device__ __forceinline__ void gbar() {
    __threadfence();
    __syncthreads();
    if (threadIdx.x == 0) {
        unsigned long long t = atomicAdd(&g_bar, 1ULL);
        unsigned long long target = t - (t % G) + G;
        volatile unsigned long long* p = &g_bar;
        while (*p < target) {}
    }
    __syncthreads();
    __threadfence();
}

__device__ __forceinline__ void hitcnt(int sval) {
    int p = atomicAdd(&g_cnt, 1);
    if (p < CAP) g_srcs[p] = sval;
}

__global__ void __launch_bounds__(B, 2) k_fused(
    const float* __restrict__ nf, const float* __restrict__ h,
    const float* __restrict__ W_enc, const float* __restrict__ b_enc,
    const float* __restrict__ W_gcn, const float* __restrict__ b_gcn,
    const float* __restrict__ W_ih, const float* __restrict__ W_hh,
    const float* __restrict__ b_ih, const float* __restrict__ b_hh,
    const unsigned* __restrict__ w, int E, int N, float* __restrict__ out)
{
    __shared__ int   sBad;
    __shared__ float sF[64];
    __shared__ int   sS[CAP];

    const int t = threadIdx.x, lane = t & 31, wid = t >> 5;
    const int bid = blockIdx.x;
    const int gid = bid * B + t;
    const int NPAD = (N + 15) & ~15;
    unsigned char* sT8 = (unsigned char*)sMem;

    // ---- init: zero u8 table + dtype detect (per block) ----
    {
        uint4* p4 = (uint4*)sMem;
        uint4 z = make_uint4(0, 0, 0, 0);
        for (int i = t; i < (NPAD >> 4); i += B) p4[i] = z;
    }
    if (t == 0) sBad = 0;
    __syncthreads();
    {
        int bad = 0;
        for (int i = t; i < 2048 && i < E; i += B) bad |= (int)w[2 * i + 1];
        if (bad) atomicOr(&sBad, 1);
    }
    __syncthreads();
    const bool is64 = (sBad == 0);
    // fast path: int64 needs E%2==0 (uint4 pairs) and E<=EMAX for compaction;
    //            int32 needs E%4==0.
    const bool fastA = is64 ? (((E & 3) == 0) && (E <= EMAX)) : ((E & 3) == 0);

    // ---------------- Pass A ----------------
    if (is64) {
        const long long* srcq = (const long long*)w;
        if (fastA) {
            const uint4* dv = (const uint4*)(w + 2L * E);  // {lo,hi,lo,hi}, E/2 vecs
            uint4* out4 = (uint4*)g_dstlo;                 // E/4 out vecs
            int nk = E >> 2;
            for (int k = gid; k < nk; k += STR) {
                uint4 a = dv[2 * k], b = dv[2 * k + 1];
                out4[k] = make_uint4(a.x, a.z, b.x, b.z);  // compact lo-words
                if (min(min(a.x, a.z), min(b.x, b.z)) == 0) {
                    long e = 4L * k;
                    if (a.x == 0) hitcnt((int)srcq[e]);
                    if (a.z == 0) hitcnt((int)srcq[e + 1]);
                    if (b.x == 0) hitcnt((int)srcq[e + 2]);
                    if (b.z == 0) hitcnt((int)srcq[e + 3]);
                }
            }
        } else {
            const long long* dst = srcq + E;
            for (long i = gid; i < E; i += STR)
                if (dst[i] == 0) hitcnt((int)srcq[i]);
        }
    } else {
        const int* srci = (const int*)w;
        if (fastA) {
            const uint4* dv = (const uint4*)(w + E);       // 4 edges per vec
            int nk = E >> 2;
            for (int k = gid; k < nk; k += STR) {
                uint4 v = dv[k];
                if (min(min(v.x, v.y), min(v.z, v.w)) == 0) {
                    long e = 4L * k;
                    if (v.x == 0) hitcnt(srci[e]);
                    if (v.y == 0) hitcnt(srci[e + 1]);
                    if (v.z == 0) hitcnt(srci[e + 2]);
                    if (v.w == 0) hitcnt(srci[e + 3]);
                }
            }
        } else {
            const int* dst = srci + E;
            for (long i = gid; i < E; i += STR)
                if (dst[i] == 0) hitcnt(srci[i]);
        }
    }
    gbar();  // -------- barrier 1 (fences compaction stores) --------

    int cnt = g_cnt; if (cnt > CAP) cnt = CAP;
    const int M = cnt + 1;                      // + node-0 self-loop term
    const bool fastB = fastA && (cnt <= 253);

    // stage srcs into smem (encoder + table build)
    for (int i = t; i < cnt; i += B) sS[i] = g_srcs[i];
    __syncthreads();

    // ---------------- Pass B: membership count (compact stream) ----------------
    if (fastB) {
        // parallel u8 table build (duplicate races are value-equivalent)
        for (int i = t; i < cnt; i += B) sT8[sS[i]] = (unsigned char)(i + 1);
        __syncthreads();
        if (t == 0 && sT8[0] == 0) sT8[0] = (unsigned char)(cnt + 1);
        __syncthreads();

        // 4 edges per uint4: g_dstlo for int64 (12.8MB), original dst for int32
        const uint4* cv = is64 ? (const uint4*)g_dstlo : (const uint4*)(w + E);
        int nk = E >> 2;
        for (int k = gid; k < nk; k += STR) {
            uint4 v = cv[k];
            unsigned p0 = sT8[v.x], p1 = sT8[v.y], p2 = sT8[v.z], p3 = sT8[v.w];
            if ((p0 | p1) | (p2 | p3)) {
                if (p0) atomicAdd(&g_nodecnt[p0 - 1], 1);
                if (p1) atomicAdd(&g_nodecnt[p1 - 1], 1);
                if (p2) atomicAdd(&g_nodecnt[p2 - 1], 1);
                if (p3) atomicAdd(&g_nodecnt[p3 - 1], 1);
            }
        }
    } else {
        // fallback: global u16 presence table + scalar scan of original dst
        for (int i = gid; i < 131072; i += STR) g_pres[i] = 0;
        gbar();
        if (bid == 0 && t == 0) {
            for (int i = 0; i < cnt; i++) g_pres[sS[i]] = (unsigned short)(i + 1);
            if (g_pres[0] == 0) g_pres[0] = (unsigned short)(cnt + 1);
        }
        gbar();
        if (is64) {
            const long long* dst = ((const long long*)w) + E;
            for (long i = gid; i < E; i += STR) {
                unsigned p = g_pres[(unsigned)dst[i]];
                if (p) atomicAdd(&g_nodecnt[p - 1], 1);
            }
        } else {
            const int* dst = ((const int*)w) + E;
            for (long i = gid; i < E; i += STR) {
                unsigned p = g_pres[(unsigned)dst[i]];
                if (p) atomicAdd(&g_nodecnt[p - 1], 1);
            }
        }
    }
    gbar();  // -------- barrier 2 --------

    // ---------------- Encoder terms (block per term) + gh overlap ----------
    if (bid < M) {
        unsigned pi0 = fastB ? (unsigned)sT8[0] : (unsigned)g_pres[0];
        const float rd0 = rsqrtf((float)g_nodecnt[pi0 - 1] + 1.0f);
        for (int i = bid; i < M; i += G) {
            int s = (i < cnt) ? sS[i] : 0;
            unsigned pis = fastB ? (unsigned)sT8[s] : (unsigned)g_pres[s];
            float wt = rsqrtf((float)g_nodecnt[pis - 1] + 1.0f) * rd0;
            if (t < 64) sF[t] = nf[(long)s * 64 + t];
            __syncthreads();
            float f0 = sF[lane], f1 = sF[lane + 32];
            #pragma unroll
            for (int jj = 0; jj < 4; jj++) {
                int j = wid * 4 + jj;
                const float* wr = W_enc + j * 64;
                float a = wr[lane] * f0 + wr[lane + 32] * f1;
                #pragma unroll
                for (int o = 16; o; o >>= 1) a += __shfl_down_sync(0xffffffffu, a, o);
                if (lane == 0) g_ybuf[i][j] = wt * fmaxf(a + b_enc[j], 0.0f);
            }
            __syncthreads();
        }
    }
    if (bid >= 272) {                     // gh = W_hh @ h + b_hh (indep of g0)
        int r = (bid - 272) * 32 + wid;   // 24 blocks x 32 warps = 768 rows
        if (r < 768) {
            const float* wr = W_hh + r * 256;
            float a = 0.0f;
            #pragma unroll
            for (int kk = 0; kk < 8; kk++) a += wr[kk * 32 + lane] * h[kk * 32 + lane];
            #pragma unroll
            for (int o = 16; o; o >>= 1) a += __shfl_down_sync(0xffffffffu, a, o);
            if (lane == 0) g_gh[r] = a + b_hh[r];
        }
    }
    gbar();  // -------- barrier 3 --------

    // ---------------- Block-0 tail: xsum, g0, gi, gates, reset -------------
    if (bid == 0) {
        float* sX   = (float*)sMem;       // table no longer needed: reuse smem
        float* sG0  = sX + 128;
        float* sGi  = sG0 + 128;          // 768 floats
        float* sPar = sX + 1024;          // 8 x 128 partials

        {   // parallel xsum, deterministic fixed-order groups
            int grp = t >> 7, col = t & 127;
            float xs = 0.0f;
            for (int i = grp; i < M; i += 8) xs += g_ybuf[i][col];
            sPar[grp * 128 + col] = xs;
        }
        __syncthreads();
        if (t < 128) {
            float s = 0.0f;
            #pragma unroll
            for (int g2 = 0; g2 < 8; g2++) s += sPar[g2 * 128 + t];
            sX[t] = s;
        }
        __syncthreads();
        #pragma unroll
        for (int jj = 0; jj < 4; jj++) {
            int j = wid * 4 + jj;
            float a = 0.0f;
            #pragma unroll
            for (int kk = 0; kk < 4; kk++)
                a += W_gcn[j * 128 + kk * 32 + lane] * sX[kk * 32 + lane];
            #pragma unroll
            for (int o = 16; o; o >>= 1) a += __shfl_down_sync(0xffffffffu, a, o);
            if (lane == 0) sG0[j] = fmaxf(a + b_gcn[j], 0.0f);
        }
        __syncthreads();
        #pragma unroll
        for (int q = 0; q < 24; q++) {
            int r = q * 32 + wid;
            const float* wr = W_ih + r * 128;
            float a = 0.0f;
            #pragma unroll
            for (int kk = 0; kk < 4; kk++)
                a += wr[kk * 32 + lane] * sG0[kk * 32 + lane];
            #pragma unroll
            for (int o = 16; o; o >>= 1) a += __shfl_down_sync(0xffffffffu, a, o);
            if (lane == 0) sGi[r] = a + b_ih[r];
        }
        __syncthreads();
        if (t < 256) {
            float r_ = 1.0f / (1.0f + expf(-(sGi[t] + g_gh[t])));
            float z  = 1.0f / (1.0f + expf(-(sGi[256 + t] + g_gh[256 + t])));
            float nn = tanhf(sGi[512 + t] + r_ * g_gh[512 + t]);
            out[t] = (1.0f - z) * nn + z * h[t];
        }
        for (int i = t; i < cnt + 2; i += B) g_nodecnt[i] = 0;
        if (t == 0) g_cnt = 0;
    }
}

// ---------------------------------------------------------------------------
extern "C" void kernel_launch(void* const* d_in, const int* in_sizes, int n_in,
                              void* d_out, int out_size) {
    const float* nf    = (const float*)d_in[0];
    // d_in[1] = edge_attr (unused by reference)
    const float* h     = (const float*)d_in[2];
    const float* W_enc = (const float*)d_in[3];
    const float* b_enc = (const float*)d_in[4];
    const float* W_gcn = (const float*)d_in[5];
    const float* b_gcn = (const float*)d_in[6];
    const float* W_ih  = (const float*)d_in[7];
    const float* W_hh  = (const float*)d_in[8];
    const float* b_ih  = (const float*)d_in[9];
    const float* b_hh  = (const float*)d_in[10];
    const unsigned* ei = (const unsigned*)d_in[11];
    int E = in_sizes[11] / 2;
    int N = in_sizes[0] / 64;
    float* out = (float*)d_out;

    int npad = (N + 15) & ~15;
    int smem = npad;
    if (smem < 16384) smem = 16384;                // room for tail reuse arrays
    cudaFuncSetAttribute(k_fused, cudaFuncAttributeMaxDynamicSharedMemorySize, smem);

    k_fused<<<G, B, smem>>>(nf, h, W_enc, b_enc, W_gcn, b_gcn,
                            W_ih, W_hh, b_ih, b_hh, ei, E, N, out);
}